// round 4
// baseline (speedup 1.0000x reference)
#include <cuda_runtime.h>
#include <math.h>

// ---------------------------------------------------------------------------
// EnBaseLayer (EGNN layer) for GB300.
//  NOTE: edge_index is int32 on the wire (JAX x64 disabled silently downcasts
//  the reference's jnp.int64 to int32). Reading it as int64 was the R2 crash.
//  Pipeline:
//   zero_kernel (graph-safe scratch zeroing; graph memset nodes can't target
//                module-scope __device__ symbols)
//   edge_kernel: per 64-edge tile: gather hi/hj, gaussian smear, 3 tiled
//                fp32 GEMMs (We1 280x128, We2 128x128, Wx1 128x128) + silu,
//                eij/xg dot heads, atomic scatter into g_mi / g_dx.
//   node_kernel: per 64-node tile: [mi,h] @ Wn1 (silu) @ Wn2 + residual,
//                plus coordinate update x + dx*mask.
// ---------------------------------------------------------------------------

#define NT   256      // threads per block
#define TE   64       // edges per block
#define TN   64       // nodes per block
#define HID  128
#define ZK   280      // 2*HID + 20 + 4
#define ZS   284      // padded stride of z tile (mult of 4 -> 16B row align)
#define MS   132      // padded stride of 128-wide smem tiles
#define NZS  260      // padded stride of node [mi,h] tile (256 + 4)
#define MAXN 50000

__device__ float g_mi[MAXN * HID];
__device__ float g_dx[MAXN * 3];

__device__ __forceinline__ float siluf(float v) {
    return v / (1.0f + __expf(-v));
}
__device__ __forceinline__ float sigmoidf_(float v) {
    return 1.0f / (1.0f + __expf(-v));
}

__global__ void zero_kernel(float* __restrict__ p, int n) {
    const int i = blockIdx.x * blockDim.x + threadIdx.x;
    const int stride = gridDim.x * blockDim.x;
    for (int k = i; k < n; k += stride) p[k] = 0.0f;
}

// Tiled GEMM: s_out[e][c] = act( sum_k s_in[e][k] * W[k][c] + b[c] )
// 64 rows x 128 cols, NT=256 threads, thread (ty,tx): 4 rows x 8 cols
// (cols tx, tx+16, ..., tx+112 -> conflict-free smem weight reads).
template<int K, int KC, int SIN, bool ACT>
__device__ __forceinline__ void tile_gemm(
    const float* __restrict__ s_in, const float* __restrict__ W,
    const float* __restrict__ b, float* __restrict__ s_out, int out_stride,
    float* __restrict__ s_w, int tid)
{
    const int ty = tid >> 4;          // 0..15  (row group of 4)
    const int tx = tid & 15;          // 0..15  (col group of 8, stride 16)
    float acc[4][8];
#pragma unroll
    for (int i = 0; i < 4; i++)
#pragma unroll
        for (int j = 0; j < 8; j++) acc[i][j] = 0.0f;

    for (int k0 = 0; k0 < K; k0 += KC) {
        __syncthreads();  // previous consumers of s_w / producers of s_in done
        for (int i = tid; i < KC * HID; i += NT)
            s_w[i] = W[k0 * HID + i];
        __syncthreads();
#pragma unroll 8
        for (int k = 0; k < KC; k++) {
            float zr[4];
#pragma unroll
            for (int i = 0; i < 4; i++)
                zr[i] = s_in[(4 * ty + i) * SIN + k0 + k];
            float wr[8];
#pragma unroll
            for (int j = 0; j < 8; j++)
                wr[j] = s_w[k * HID + tx + 16 * j];
#pragma unroll
            for (int i = 0; i < 4; i++)
#pragma unroll
                for (int j = 0; j < 8; j++)
                    acc[i][j] = fmaf(zr[i], wr[j], acc[i][j]);
        }
    }
#pragma unroll
    for (int i = 0; i < 4; i++) {
#pragma unroll
        for (int j = 0; j < 8; j++) {
            const int c = tx + 16 * j;
            float v = acc[i][j] + b[c];
            if (ACT) v = siluf(v);
            s_out[(4 * ty + i) * out_stride + c] = v;
        }
    }
}

// smem layout sizes (floats)
#define EDGE_SMEM_F (TE*ZS + 64*HID + TE*MS + TE*MS + TE*3 + TE + TE + TE + TE + TE)
#define NODE_SMEM_F (TN*NZS + 64*HID + TN*MS)

__global__ __launch_bounds__(NT, 1)
void edge_kernel(const float* __restrict__ h, const float* __restrict__ x,
                 const int* __restrict__ eidx,
                 const float* __restrict__ eattr,
                 const float* __restrict__ We1, const float* __restrict__ be1,
                 const float* __restrict__ We2, const float* __restrict__ be2,
                 const float* __restrict__ Winf, const float* __restrict__ binf,
                 const float* __restrict__ Wx1, const float* __restrict__ bx1,
                 const float* __restrict__ Wx2,
                 int E)
{
    extern __shared__ float sm[];
    float* s_z   = sm;                    // TE*ZS : z tile [hi|hj|dfeat|eattr]
    float* s_w   = s_z + TE * ZS;         // 64*HID: weight staging
    float* s_a   = s_w + 64 * HID;        // TE*MS : layer-1 out / hx
    float* s_m   = s_a + TE * MS;         // TE*MS : mij
    float* s_rel = s_m + TE * MS;         // TE*3
    float* s_d   = s_rel + TE * 3;        // TE
    float* s_e   = s_d + TE;              // TE : eij (0 for invalid edges)
    float* s_g   = s_e + TE;              // TE : xg  (0 for invalid edges)
    int*   s_dst = (int*)(s_g + TE);      // TE
    int*   s_src = (int*)(s_dst + TE);    // TE

    const int tid = threadIdx.x;
    const int e0  = blockIdx.x * TE;

    // ---- per-edge meta: indices, rel_x, distance, gaussian smearing ----
    if (tid < TE) {
        const int e = e0 + tid;
        int src = 0, dst = 0;
        float d = 1.0f, rx = 0.f, ry = 0.f, rz = 0.f;
        if (e < E) {
            src = eidx[e];          // row 0 of edge_index (int32!)
            dst = eidx[E + e];      // row 1 of edge_index
            rx = x[dst * 3 + 0] - x[src * 3 + 0];
            ry = x[dst * 3 + 1] - x[src * 3 + 1];
            rz = x[dst * 3 + 2] - x[src * 3 + 2];
            d  = sqrtf(rx * rx + ry * ry + rz * rz + 1e-8f);
        }
        s_src[tid] = src;
        s_dst[tid] = dst;
        s_rel[tid * 3 + 0] = rx;
        s_rel[tid * 3 + 1] = ry;
        s_rel[tid * 3 + 2] = rz;
        s_d[tid] = d;
        const float step  = 10.0f / 19.0f;
        const float coeff = -0.5f / (step * step);
#pragma unroll
        for (int g = 0; g < 20; g++) {
            const float t = d - step * (float)g;
            s_z[tid * ZS + 2 * HID + g] = __expf(coeff * t * t);
        }
        float4 ea = make_float4(0.f, 0.f, 0.f, 0.f);
        if (e < E) ea = *(const float4*)(eattr + (size_t)e * 4);
        s_z[tid * ZS + 2 * HID + 20] = ea.x;
        s_z[tid * ZS + 2 * HID + 21] = ea.y;
        s_z[tid * ZS + 2 * HID + 22] = ea.z;
        s_z[tid * ZS + 2 * HID + 23] = ea.w;
    }
    __syncthreads();

    // ---- gather hi = h[dst] -> z[:,0:128], hj = h[src] -> z[:,128:256] ----
    for (int idx = tid; idx < TE * 32; idx += NT) {
        const int e = idx >> 5, q = idx & 31;
        float4 vi = *(const float4*)(h + (size_t)s_dst[e] * HID + 4 * q);
        *(float4*)(s_z + e * ZS + 4 * q) = vi;
        float4 vj = *(const float4*)(h + (size_t)s_src[e] * HID + 4 * q);
        *(float4*)(s_z + e * ZS + HID + 4 * q) = vj;
    }
    // (tile_gemm's leading __syncthreads orders this before first use)

    // ---- edge MLP layer 1: silu(z @ We1 + be1) -> s_a ----
    tile_gemm<ZK, 56, ZS, true>(s_z, We1, be1, s_a, MS, s_w, tid);
    // ---- edge MLP layer 2: mij = silu(a1 @ We2 + be2) -> s_m ----
    tile_gemm<HID, 64, MS, true>(s_a, We2, be2, s_m, MS, s_w, tid);
    __syncthreads();

    // ---- eij = sigmoid(mij . Winf + binf) ----
    if (tid < TE) {
        float s = 0.0f;
#pragma unroll 8
        for (int k = 0; k < HID; k++)
            s = fmaf(s_m[tid * MS + k], __ldg(Winf + k), s);
        const bool valid = (e0 + tid) < E;
        s_e[tid] = valid ? sigmoidf_(s + __ldg(binf)) : 0.0f;
    }

    // ---- coord head: hx = silu(mij @ Wx1 + bx1) -> s_a (reuse) ----
    tile_gemm<HID, 64, MS, true>(s_m, Wx1, bx1, s_a, MS, s_w, tid);
    __syncthreads();

    // ---- xg = tanh(hx . Wx2) ----
    if (tid < TE) {
        float s = 0.0f;
#pragma unroll 8
        for (int k = 0; k < HID; k++)
            s = fmaf(s_a[tid * MS + k], __ldg(Wx2 + k), s);
        const bool valid = (e0 + tid) < E;
        s_g[tid] = valid ? tanhf(s) : 0.0f;
    }
    __syncthreads();

    // ---- scatter: mi[dst] += mij * eij ----
    for (int idx = tid; idx < TE * HID; idx += NT) {
        const int e = idx >> 7, c = idx & (HID - 1);
        const float v = s_m[e * MS + c] * s_e[e];
        atomicAdd(&g_mi[(size_t)s_dst[e] * HID + c], v);
    }
    // ---- scatter: dx[dst] += rel_x / (d+1) * xg ----
    if (tid < TE) {
        const float fac = s_g[tid] / (s_d[tid] + 1.0f);
        const int dst = s_dst[tid];
#pragma unroll
        for (int c = 0; c < 3; c++)
            atomicAdd(&g_dx[(size_t)dst * 3 + c], s_rel[tid * 3 + c] * fac);
    }
}

__global__ __launch_bounds__(NT, 1)
void node_kernel(const float* __restrict__ h, const float* __restrict__ x,
                 const float* __restrict__ mask,
                 const float* __restrict__ Wn1, const float* __restrict__ bn1,
                 const float* __restrict__ Wn2, const float* __restrict__ bn2,
                 float* __restrict__ out_h, float* __restrict__ out_x, int N)
{
    extern __shared__ float sm[];
    float* s_nz = sm;                   // TN*NZS : [mi | h]
    float* s_w  = s_nz + TN * NZS;      // 64*HID
    float* s_a  = s_w + 64 * HID;       // TN*MS

    const int tid = threadIdx.x;
    const int n0  = blockIdx.x * TN;

    // gather [mi, h]
    for (int idx = tid; idx < TN * 32; idx += NT) {
        const int r = idx >> 5, q = idx & 31;
        const int n = n0 + r;
        float4 vm = make_float4(0.f, 0.f, 0.f, 0.f);
        float4 vh = vm;
        if (n < N) {
            vm = *(const float4*)(g_mi + (size_t)n * HID + 4 * q);
            vh = *(const float4*)(h + (size_t)n * HID + 4 * q);
        }
        *(float4*)(s_nz + r * NZS + 4 * q)       = vm;
        *(float4*)(s_nz + r * NZS + HID + 4 * q) = vh;
    }

    // layer 1: silu([mi,h] @ Wn1 + bn1) -> s_a
    tile_gemm<2 * HID, 64, NZS, true>(s_nz, Wn1, bn1, s_a, MS, s_w, tid);
    // layer 2: (a @ Wn2 + bn2) -> s_nz (reuse, stride NZS)
    tile_gemm<HID, 64, MS, false>(s_a, Wn2, bn2, s_nz, NZS, s_w, tid);
    __syncthreads();

    // h_out = h + result
    for (int idx = tid; idx < TN * HID; idx += NT) {
        const int r = idx >> 7, c = idx & (HID - 1);
        const int n = n0 + r;
        if (n < N)
            out_h[(size_t)n * HID + c] = h[(size_t)n * HID + c] + s_nz[r * NZS + c];
    }
    // x_out = x + dx * mask
    if (tid < TN) {
        const int n = n0 + tid;
        if (n < N) {
            const float m = mask[n];
#pragma unroll
            for (int c = 0; c < 3; c++)
                out_x[(size_t)n * 3 + c] =
                    x[(size_t)n * 3 + c] + g_dx[(size_t)n * 3 + c] * m;
        }
    }
}

extern "C" void kernel_launch(void* const* d_in, const int* in_sizes, int n_in,
                              void* d_out, int out_size)
{
    const float* h     = (const float*)d_in[0];
    const float* x     = (const float*)d_in[1];
    const int*   eidx  = (const int*)d_in[2];   // int32 (JAX x64 disabled)
    const float* mask  = (const float*)d_in[3];
    const float* eattr = (const float*)d_in[4];
    const float* We1   = (const float*)d_in[5];
    const float* be1   = (const float*)d_in[6];
    const float* We2   = (const float*)d_in[7];
    const float* be2   = (const float*)d_in[8];
    const float* Winf  = (const float*)d_in[9];
    const float* binf  = (const float*)d_in[10];
    const float* Wx1   = (const float*)d_in[11];
    const float* bx1   = (const float*)d_in[12];
    const float* Wx2   = (const float*)d_in[13];
    const float* Wn1   = (const float*)d_in[14];
    const float* bn1   = (const float*)d_in[15];
    const float* Wn2   = (const float*)d_in[16];
    const float* bn2   = (const float*)d_in[17];

    const int N = in_sizes[0] / HID;
    const int E = in_sizes[2] / 2;
    float* out   = (float*)d_out;
    float* out_h = out;
    float* out_x = out + (size_t)N * HID;

    // Zero scratch via kernel launch (graph memset nodes cannot target
    // module-scope __device__ symbols).
    void* mi_ptr = nullptr;
    void* dx_ptr = nullptr;
    cudaGetSymbolAddress(&mi_ptr, g_mi);
    cudaGetSymbolAddress(&dx_ptr, g_dx);
    zero_kernel<<<592, 256>>>((float*)mi_ptr, N * HID);
    zero_kernel<<<64, 256>>>((float*)dx_ptr, N * 3);

    const size_t edge_smem = (size_t)EDGE_SMEM_F * sizeof(float);
    const size_t node_smem = (size_t)NODE_SMEM_F * sizeof(float);
    cudaFuncSetAttribute(edge_kernel,
                         cudaFuncAttributeMaxDynamicSharedMemorySize,
                         (int)edge_smem);
    cudaFuncSetAttribute(node_kernel,
                         cudaFuncAttributeMaxDynamicSharedMemorySize,
                         (int)node_smem);

    const int eb = (E + TE - 1) / TE;
    edge_kernel<<<eb, NT, edge_smem>>>(h, x, eidx, eattr,
                                       We1, be1, We2, be2,
                                       Winf, binf, Wx1, bx1, Wx2, E);

    const int nb = (N + TN - 1) / TN;
    node_kernel<<<nb, NT, node_smem>>>(h, x, mask, Wn1, bn1, Wn2, bn2,
                                       out_h, out_x, N);
}